// round 15
// baseline (speedup 1.0000x reference)
#include <cuda_runtime.h>
#include <math.h>
#include <stdint.h>

// ---------------------------------------------------------------------------
// Problem constants (shapes fixed by the dataset; guarded at runtime anyway)
// ---------------------------------------------------------------------------
#define NU_MAX 200000
#define NI_MAX 20000
#define E_MAX  1000000
#define NEG_SLOPE 0.2f
#define SCAN_TILE 4096   // elements per scan block (256 thr x 16)
#define MAX_SCAN_BLOCKS 64

// ---------------------------------------------------------------------------
// Scratch (device globals -- no allocation allowed)
// ---------------------------------------------------------------------------
__device__ float g_user_x[NU_MAX * 32];
__device__ float g_item_x[NI_MAX * 32];
__device__ float g_xl1[NU_MAX * 128];
__device__ float g_xr1[NI_MAX * 128];
__device__ float g_item_h[NI_MAX * 128];
__device__ float g_xl2[NI_MAX * 128];
__device__ float g_xr2[NU_MAX * 128];
__device__ float g_tmp[NU_MAX * 128];

__device__ int g_cnt1[NI_MAX];
__device__ int g_off1[NI_MAX + 1];
__device__ int g_cur1[NI_MAX];
__device__ int g_cnt2[NU_MAX];
__device__ int g_off2[NU_MAX + 1];
__device__ int g_cur2[NU_MAX];
__device__ int g_c1_src[E_MAX];
__device__ int g_c1_eid[E_MAX];
__device__ int g_c2_item[E_MAX];
__device__ int g_bsums1[MAX_SCAN_BLOCKS];
__device__ int g_bsums2[MAX_SCAN_BLOCKS];

// ---------------------------------------------------------------------------
// CSR build
// ---------------------------------------------------------------------------
__global__ void zero_counts_kernel(int n1, int n2) {
    int i = blockIdx.x * blockDim.x + threadIdx.x;
    if (i < n1) g_cnt1[i] = 0;
    if (i < n2) g_cnt2[i] = 0;
}

__global__ void hist_kernel(const int* __restrict__ src,
                            const int* __restrict__ dst, int E) {
    int e = blockIdx.x * blockDim.x + threadIdx.x;
    if (e < E) {
        atomicAdd(&g_cnt1[dst[e]], 1);
        atomicAdd(&g_cnt2[src[e]], 1);
    }
}

// ---- multi-block exclusive scan: A) block partial sums --------------------
__global__ __launch_bounds__(256) void scan_part_kernel(
    const int* __restrict__ cnt, int* __restrict__ bsums, int n) {
    __shared__ int red[256];
    int base = blockIdx.x * SCAN_TILE;
    int t = threadIdx.x;
    int s = 0;
#pragma unroll
    for (int j = 0; j < 16; j++) {
        int idx = base + j * 256 + t;
        if (idx < n) s += cnt[idx];
    }
    red[t] = s;
    __syncthreads();
#pragma unroll
    for (int d = 128; d; d >>= 1) {
        if (t < d) red[t] += red[t + d];
        __syncthreads();
    }
    if (t == 0) bsums[blockIdx.x] = red[0];
}

// ---- B) exclusive scan of the (<=64) block sums, in place -----------------
__global__ void scan_bsums_kernel(int* __restrict__ bsums, int nb) {
    __shared__ int sh[MAX_SCAN_BLOCKS];
    int t = threadIdx.x;
    int own = (t < nb) ? bsums[t] : 0;
    sh[t] = own;
    __syncthreads();
#pragma unroll
    for (int d = 1; d < MAX_SCAN_BLOCKS; d <<= 1) {
        int v = (t >= d) ? sh[t - d] : 0;
        __syncthreads();
        sh[t] += v;
        __syncthreads();
    }
    if (t < nb) bsums[t] = sh[t] - own;  // exclusive
}

// ---- C) per-block rescan + add block offset, write off/cur ----------------
__global__ __launch_bounds__(256) void scan_final_kernel(
    const int* __restrict__ cnt, const int* __restrict__ bsums,
    int* __restrict__ off, int* __restrict__ cur, int n) {
    __shared__ int vals[SCAN_TILE];
    __shared__ int tsum[256];
    int base = blockIdx.x * SCAN_TILE;
    int t = threadIdx.x;
    // coalesced stage into smem
#pragma unroll
    for (int j = 0; j < 16; j++) {
        int idx = base + j * 256 + t;
        vals[j * 256 + t] = (idx < n) ? cnt[idx] : 0;
    }
    __syncthreads();
    // serial exclusive scan of this thread's 16 contiguous values
    int loc[16];
    int s = 0;
#pragma unroll
    for (int j = 0; j < 16; j++) {
        loc[j] = s;
        s += vals[t * 16 + j];
    }
    int own = s;
    tsum[t] = s;
    __syncthreads();
    // inclusive Hillis-Steele over thread sums
#pragma unroll
    for (int d = 1; d < 256; d <<= 1) {
        int v = (t >= d) ? tsum[t - d] : 0;
        __syncthreads();
        tsum[t] += v;
        __syncthreads();
    }
    int pre = tsum[t] - own + bsums[blockIdx.x];
#pragma unroll
    for (int j = 0; j < 16; j++) {
        int idx = base + t * 16 + j;
        if (idx < n) {
            int v = pre + loc[j];
            off[idx] = v;
            cur[idx] = v;
        }
    }
    // grand total -> off[n] (out-of-range cnt treated as 0, so this is exact)
    if (blockIdx.x == gridDim.x - 1 && t == 255) off[n] = pre + own;
}

__global__ void scatter_kernel(const int* __restrict__ src,
                               const int* __restrict__ dst, int E) {
    int e = blockIdx.x * blockDim.x + threadIdx.x;
    if (e < E) {
        int d = dst[e];
        int s = src[e];
        int p = atomicAdd(&g_cur1[d], 1);
        g_c1_src[p] = s;
        g_c1_eid[p] = e;
        int q = atomicAdd(&g_cur2[s], 1);
        g_c2_item[q] = d;
    }
}

// ---------------------------------------------------------------------------
// Input linears
// ---------------------------------------------------------------------------
// user_x = customer_x[2e5,101] @ w[101,32] + b    (8 rows x 32 cols per block)
__global__ __launch_bounds__(256) void user_lin_kernel(
    const float* __restrict__ x, const float* __restrict__ w,
    const float* __restrict__ b, int M) {
    __shared__ float ws[101 * 32];
    __shared__ float bs[32];
    for (int i = threadIdx.x; i < 101 * 32; i += 256) ws[i] = w[i];
    if (threadIdx.x < 32) bs[threadIdx.x] = b[threadIdx.x];
    __syncthreads();
    int c = threadIdx.x & 31;
    int r = blockIdx.x * 8 + (threadIdx.x >> 5);
    if (r >= M) return;
    const float* xr = x + (size_t)r * 101;
    float acc = bs[c];
#pragma unroll 4
    for (int k = 0; k < 101; k++) acc = fmaf(xr[k], ws[k * 32 + c], acc);
    g_user_x[(size_t)r * 32 + c] = acc;
}

// item_x = fund_x[2e4,1] @ w[1,32] + b
__global__ void item_lin_kernel(const float* __restrict__ fx,
                                const float* __restrict__ w,
                                const float* __restrict__ b, int Ni) {
    int i = blockIdx.x * blockDim.x + threadIdx.x;
    if (i < Ni * 32) {
        int r = i >> 5, c = i & 31;
        g_item_x[i] = fmaf(fx[r], w[c], b[c]);
    }
}

// ---------------------------------------------------------------------------
// Register-tiled SGEMM: C[M,128] = A[M,K] @ W[K,128] + bias,  K in {32,128}
// BM=128, BN=128, BK=16, 256 threads, 8x8 micro-tile per thread
// ---------------------------------------------------------------------------
template <int K, bool RELU>
__global__ __launch_bounds__(256, 2) void sgemm_n128(
    const float* __restrict__ A, const float* __restrict__ W,
    const float* __restrict__ bias, float* __restrict__ C, int M) {
    __shared__ float As[16][132];  // [k][row], padded
    __shared__ float Ws[16][128];  // [k][col]
    const int tid = threadIdx.x;
    const int tx = tid & 15;   // col group
    const int ty = tid >> 4;   // row group
    const int row0 = blockIdx.x * 128;

    float acc[8][8];
#pragma unroll
    for (int i = 0; i < 8; i++)
#pragma unroll
        for (int j = 0; j < 8; j++) acc[i][j] = 0.f;

    for (int k0 = 0; k0 < K; k0 += 16) {
        // A tile: 128 rows x 16 cols, transposed into As[k][row]
#pragma unroll
        for (int uu = tid; uu < 512; uu += 256) {
            int arow = uu >> 2;
            int ac = (uu & 3) << 2;
            float4 v = make_float4(0.f, 0.f, 0.f, 0.f);
            int gr = row0 + arow;
            if (gr < M) v = *(const float4*)(A + (size_t)gr * K + k0 + ac);
            As[ac + 0][arow] = v.x;
            As[ac + 1][arow] = v.y;
            As[ac + 2][arow] = v.z;
            As[ac + 3][arow] = v.w;
        }
        // W tile: 16 rows x 128 cols
#pragma unroll
        for (int uu = tid; uu < 512; uu += 256) {
            int wr = uu >> 5;
            int wc = (uu & 31) << 2;
            *(float4*)&Ws[wr][wc] =
                *(const float4*)(W + (size_t)(k0 + wr) * 128 + wc);
        }
        __syncthreads();
#pragma unroll
        for (int k = 0; k < 16; k++) {
            float4 a0 = *(const float4*)&As[k][ty * 8];
            float4 a1 = *(const float4*)&As[k][ty * 8 + 4];
            float4 w0 = *(const float4*)&Ws[k][tx * 4];
            float4 w1 = *(const float4*)&Ws[k][64 + tx * 4];
            float a[8] = {a0.x, a0.y, a0.z, a0.w, a1.x, a1.y, a1.z, a1.w};
            float w[8] = {w0.x, w0.y, w0.z, w0.w, w1.x, w1.y, w1.z, w1.w};
#pragma unroll
            for (int i = 0; i < 8; i++)
#pragma unroll
                for (int j = 0; j < 8; j++) acc[i][j] = fmaf(a[i], w[j], acc[i][j]);
        }
        __syncthreads();
    }

    float b0[4], b1[4];
#pragma unroll
    for (int j = 0; j < 4; j++) {
        b0[j] = bias[tx * 4 + j];
        b1[j] = bias[64 + tx * 4 + j];
    }
#pragma unroll
    for (int i = 0; i < 8; i++) {
        int gr = row0 + ty * 8 + i;
        if (gr < M) {
            float4 o0, o1;
            o0.x = acc[i][0] + b0[0]; o0.y = acc[i][1] + b0[1];
            o0.z = acc[i][2] + b0[2]; o0.w = acc[i][3] + b0[3];
            o1.x = acc[i][4] + b1[0]; o1.y = acc[i][5] + b1[1];
            o1.z = acc[i][6] + b1[2]; o1.w = acc[i][7] + b1[3];
            if (RELU) {
                o0.x = fmaxf(o0.x, 0.f); o0.y = fmaxf(o0.y, 0.f);
                o0.z = fmaxf(o0.z, 0.f); o0.w = fmaxf(o0.w, 0.f);
                o1.x = fmaxf(o1.x, 0.f); o1.y = fmaxf(o1.y, 0.f);
                o1.z = fmaxf(o1.z, 0.f); o1.w = fmaxf(o1.w, 0.f);
            }
            *(float4*)(C + (size_t)gr * 128 + tx * 4) = o0;
            *(float4*)(C + (size_t)gr * 128 + 64 + tx * 4) = o1;
        }
    }
}

// ---------------------------------------------------------------------------
// GATv2 edge aggregation, online softmax. One 128-thread CTA per dest node.
// warp = head h (4 heads), lane = channel c (32).
// ---------------------------------------------------------------------------
__global__ __launch_bounds__(128) void conv1_edge_kernel(
    const float* __restrict__ edge_attr, const float* __restrict__ we,
    const float* __restrict__ att, const float* __restrict__ bias) {
    int d = blockIdx.x;
    int tid = threadIdx.x;
    float xr   = g_xr1[d * 128 + tid];
    float attv = att[tid];
    float we0 = we[tid], we1 = we[128 + tid], we2 = we[256 + tid];
    int beg = g_off1[d], end = g_off1[d + 1];

    float m = -INFINITY, s = 0.f, acc = 0.f;

    float xlv = 0.f, e0 = 0.f, e1 = 0.f, e2 = 0.f;
    if (beg < end) {
        int srcn = g_c1_src[beg];
        int eid  = g_c1_eid[beg];
        xlv = g_xl1[(size_t)srcn * 128 + tid];
        e0 = edge_attr[(size_t)eid * 3 + 0];
        e1 = edge_attr[(size_t)eid * 3 + 1];
        e2 = edge_attr[(size_t)eid * 3 + 2];
    }
    for (int i = beg; i < end; i++) {
        float cxl = xlv, c0 = e0, c1 = e1, c2 = e2;
        int ni = i + 1;
        if (ni < end) {  // prefetch next edge while computing current
            int srcn = g_c1_src[ni];
            int eid  = g_c1_eid[ni];
            xlv = g_xl1[(size_t)srcn * 128 + tid];
            e0 = edge_attr[(size_t)eid * 3 + 0];
            e1 = edge_attr[(size_t)eid * 3 + 1];
            e2 = edge_attr[(size_t)eid * 3 + 2];
        }
        float mv = cxl + xr;
        mv = fmaf(c0, we0, mv);
        mv = fmaf(c1, we1, mv);
        mv = fmaf(c2, we2, mv);
        float g = mv > 0.f ? mv : NEG_SLOPE * mv;
        float p = g * attv;
#pragma unroll
        for (int o = 16; o; o >>= 1) p += __shfl_xor_sync(0xffffffffu, p, o);
        float logit = p;                     // same across the warp (= head)
        float nm = fmaxf(m, logit);
        float scale = __expf(m - nm);        // 0 when m == -inf
        float ev = __expf(logit - nm);
        s = s * scale + ev;
        acc = fmaf(ev, cxl, acc * scale);
        m = nm;
    }
    float o = (s > 0.f) ? acc / s : 0.f;
    o += bias[tid];
    g_item_h[d * 128 + tid] = fmaxf(o, 0.f);   // conv1 output has ReLU
}

__global__ __launch_bounds__(128) void conv2_edge_kernel(
    const float* __restrict__ att, const float* __restrict__ bias,
    float* __restrict__ user_out) {
    int u = blockIdx.x;
    int tid = threadIdx.x;
    float xr   = g_xr2[(size_t)u * 128 + tid];
    float attv = att[tid];
    int beg = g_off2[u], end = g_off2[u + 1];

    float m = -INFINITY, s = 0.f, acc = 0.f;

    float xlv = 0.f;
    if (beg < end) xlv = g_xl2[(size_t)g_c2_item[beg] * 128 + tid];
    for (int i = beg; i < end; i++) {
        float cxl = xlv;
        int ni = i + 1;
        if (ni < end) xlv = g_xl2[(size_t)g_c2_item[ni] * 128 + tid];
        float mv = cxl + xr;
        float g = mv > 0.f ? mv : NEG_SLOPE * mv;
        float p = g * attv;
#pragma unroll
        for (int o = 16; o; o >>= 1) p += __shfl_xor_sync(0xffffffffu, p, o);
        float logit = p;
        float nm = fmaxf(m, logit);
        float scale = __expf(m - nm);
        float ev = __expf(logit - nm);
        s = s * scale + ev;
        acc = fmaf(ev, cxl, acc * scale);
        m = nm;
    }
    float o = (s > 0.f) ? acc / s : 0.f;
    user_out[(size_t)u * 128 + tid] = o + bias[tid];  // no ReLU on conv2 output
}

// ---------------------------------------------------------------------------
// Launch
// ---------------------------------------------------------------------------
extern "C" void kernel_launch(void* const* d_in, const int* in_sizes, int n_in,
                              void* d_out, int out_size) {
    const float* customer_x = (const float*)d_in[0];
    const float* fund_x     = (const float*)d_in[1];
    const float* edge_attr  = (const float*)d_in[2];
    const float* user_lin_w = (const float*)d_in[3];
    const float* user_lin_b = (const float*)d_in[4];
    const float* item_lin_w = (const float*)d_in[5];
    const float* item_lin_b = (const float*)d_in[6];
    const float* conv1_wl   = (const float*)d_in[7];
    const float* conv1_bl   = (const float*)d_in[8];
    const float* conv1_wr   = (const float*)d_in[9];
    const float* conv1_br   = (const float*)d_in[10];
    const float* conv1_we   = (const float*)d_in[11];
    const float* conv1_att  = (const float*)d_in[12];
    const float* conv1_bias = (const float*)d_in[13];
    const float* conv2_wl   = (const float*)d_in[14];
    const float* conv2_bl   = (const float*)d_in[15];
    const float* conv2_wr   = (const float*)d_in[16];
    const float* conv2_br   = (const float*)d_in[17];
    const float* conv2_att  = (const float*)d_in[18];
    const float* conv2_bias = (const float*)d_in[19];
    const float* proj_w1    = (const float*)d_in[20];
    const float* proj_b1    = (const float*)d_in[21];
    const float* proj_w2    = (const float*)d_in[22];
    const float* proj_b2    = (const float*)d_in[23];
    const int*   edge_src   = (const int*)d_in[24];
    const int*   edge_dst   = (const int*)d_in[25];

    const int Nu = in_sizes[0] / 101;
    const int Ni = in_sizes[1];
    const int E  = in_sizes[24];

    float* user_out = (float*)d_out;                       // [Nu,128]
    float* z_out    = (float*)d_out + (size_t)Nu * 128;    // [Nu,128]

    const int TB = 256;
    const int gE = (E + TB - 1) / TB;

    // --- CSR build ---
    zero_counts_kernel<<<(Nu + TB - 1) / TB, TB>>>(Ni, Nu);
    hist_kernel<<<gE, TB>>>(edge_src, edge_dst, E);
    {
        int *cnt1, *off1, *cur1, *cnt2, *off2, *cur2, *bs1, *bs2;
        cudaGetSymbolAddress((void**)&cnt1, g_cnt1);
        cudaGetSymbolAddress((void**)&off1, g_off1);
        cudaGetSymbolAddress((void**)&cur1, g_cur1);
        cudaGetSymbolAddress((void**)&cnt2, g_cnt2);
        cudaGetSymbolAddress((void**)&off2, g_off2);
        cudaGetSymbolAddress((void**)&cur2, g_cur2);
        cudaGetSymbolAddress((void**)&bs1, g_bsums1);
        cudaGetSymbolAddress((void**)&bs2, g_bsums2);
        int nb1 = (Ni + SCAN_TILE - 1) / SCAN_TILE;
        int nb2 = (Nu + SCAN_TILE - 1) / SCAN_TILE;
        scan_part_kernel<<<nb1, 256>>>(cnt1, bs1, Ni);
        scan_part_kernel<<<nb2, 256>>>(cnt2, bs2, Nu);
        scan_bsums_kernel<<<1, MAX_SCAN_BLOCKS>>>(bs1, nb1);
        scan_bsums_kernel<<<1, MAX_SCAN_BLOCKS>>>(bs2, nb2);
        scan_final_kernel<<<nb1, 256>>>(cnt1, bs1, off1, cur1, Ni);
        scan_final_kernel<<<nb2, 256>>>(cnt2, bs2, off2, cur2, Nu);
    }
    scatter_kernel<<<gE, TB>>>(edge_src, edge_dst, E);

    // --- input linears ---
    user_lin_kernel<<<(Nu + 7) / 8, 256>>>(customer_x, user_lin_w, user_lin_b, Nu);
    item_lin_kernel<<<(Ni * 32 + TB - 1) / TB, TB>>>(fund_x, item_lin_w, item_lin_b, Ni);

    // --- conv1 projections ---
    {
        float *ux, *ix, *xl1, *xr1;
        cudaGetSymbolAddress((void**)&ux, g_user_x);
        cudaGetSymbolAddress((void**)&ix, g_item_x);
        cudaGetSymbolAddress((void**)&xl1, g_xl1);
        cudaGetSymbolAddress((void**)&xr1, g_xr1);
        sgemm_n128<32, false><<<(Nu + 127) / 128, 256>>>(ux, conv1_wl, conv1_bl, xl1, Nu);
        sgemm_n128<32, false><<<(Ni + 127) / 128, 256>>>(ix, conv1_wr, conv1_br, xr1, Ni);
    }

    // --- conv1 edge aggregation (user -> item), fused edge_proj, ReLU ---
    conv1_edge_kernel<<<Ni, 128>>>(edge_attr, conv1_we, conv1_att, conv1_bias);

    // --- conv2 projections ---
    {
        float *ih, *ux, *xl2, *xr2;
        cudaGetSymbolAddress((void**)&ih, g_item_h);
        cudaGetSymbolAddress((void**)&ux, g_user_x);
        cudaGetSymbolAddress((void**)&xl2, g_xl2);
        cudaGetSymbolAddress((void**)&xr2, g_xr2);
        sgemm_n128<128, false><<<(Ni + 127) / 128, 256>>>(ih, conv2_wl, conv2_bl, xl2, Ni);
        sgemm_n128<32, false><<<(Nu + 127) / 128, 256>>>(ux, conv2_wr, conv2_br, xr2, Nu);
    }

    // --- conv2 edge aggregation (item -> user) -> user_out (first output) ---
    conv2_edge_kernel<<<Nu, 128>>>(conv2_att, conv2_bias, user_out);

    // --- projection head: z = relu(user_out @ W1 + b1) @ W2 + b2 ---
    {
        float* tmp;
        cudaGetSymbolAddress((void**)&tmp, g_tmp);
        sgemm_n128<128, true><<<(Nu + 127) / 128, 256>>>(user_out, proj_w1, proj_b1, tmp, Nu);
        sgemm_n128<128, false><<<(Nu + 127) / 128, 256>>>(tmp, proj_w2, proj_b2, z_out, Nu);
    }
}

// round 16
// speedup vs baseline: 1.0575x; 1.0575x over previous
#include <cuda_runtime.h>
#include <math.h>
#include <stdint.h>

// ---------------------------------------------------------------------------
// Problem constants (shapes fixed by the dataset; guarded at runtime anyway)
// ---------------------------------------------------------------------------
#define NU_MAX 200000
#define NI_MAX 20000
#define E_MAX  1000000
#define NEG_SLOPE 0.2f
#define SCAN_TILE 4096   // elements per scan block (256 thr x 16)
#define MAX_SCAN_BLOCKS 64

// ---------------------------------------------------------------------------
// Scratch (device globals -- no allocation allowed)
// ---------------------------------------------------------------------------
__device__ float g_user_x[NU_MAX * 32];
__device__ float g_item_x[NI_MAX * 32];
__device__ float g_xl1[NU_MAX * 128];
__device__ float g_xr1[NI_MAX * 128];
__device__ float g_item_h[NI_MAX * 128];
__device__ float g_xl2[NI_MAX * 128];
__device__ float g_xr2[NU_MAX * 128];
__device__ float g_tmp[NU_MAX * 128];

__device__ int g_cnt1[NI_MAX];
__device__ int g_off1[NI_MAX + 1];
__device__ int g_cur1[NI_MAX];
__device__ int g_cnt2[NU_MAX];
__device__ int g_off2[NU_MAX + 1];
__device__ int g_cur2[NU_MAX];
__device__ int g_c1_src[E_MAX];
__device__ int g_c1_eid[E_MAX];
__device__ int g_c2_item[E_MAX];
__device__ int g_bsums1[MAX_SCAN_BLOCKS];
__device__ int g_bsums2[MAX_SCAN_BLOCKS];

// ---------------------------------------------------------------------------
// Packed f32x2 helpers (sm_103a FFMA2 -- PTX-only, ptxas never auto-fuses)
// ---------------------------------------------------------------------------
__device__ __forceinline__ void fma2(unsigned long long& acc,
                                     unsigned long long a,
                                     unsigned long long b) {
    asm("fma.rn.f32x2 %0, %1, %2, %0;" : "+l"(acc) : "l"(a), "l"(b));
}
__device__ __forceinline__ unsigned long long bcast2(float x) {
    unsigned long long r;
    asm("mov.b64 %0, {%1, %1};" : "=l"(r) : "f"(x));
    return r;
}
__device__ __forceinline__ void unpack2(unsigned long long v, float& lo, float& hi) {
    asm("mov.b64 {%0, %1}, %2;" : "=f"(lo), "=f"(hi) : "l"(v));
}

// ---------------------------------------------------------------------------
// CSR build
// ---------------------------------------------------------------------------
__global__ void zero_counts_kernel(int n1, int n2) {
    int i = blockIdx.x * blockDim.x + threadIdx.x;
    if (i < n1) g_cnt1[i] = 0;
    if (i < n2) g_cnt2[i] = 0;
}

__global__ void hist_kernel(const int* __restrict__ src,
                            const int* __restrict__ dst, int E) {
    int e = blockIdx.x * blockDim.x + threadIdx.x;
    if (e < E) {
        atomicAdd(&g_cnt1[dst[e]], 1);
        atomicAdd(&g_cnt2[src[e]], 1);
    }
}

// ---- multi-block exclusive scan: A) block partial sums --------------------
__global__ __launch_bounds__(256) void scan_part_kernel(
    const int* __restrict__ cnt, int* __restrict__ bsums, int n) {
    __shared__ int red[256];
    int base = blockIdx.x * SCAN_TILE;
    int t = threadIdx.x;
    int s = 0;
#pragma unroll
    for (int j = 0; j < 16; j++) {
        int idx = base + j * 256 + t;
        if (idx < n) s += cnt[idx];
    }
    red[t] = s;
    __syncthreads();
#pragma unroll
    for (int d = 128; d; d >>= 1) {
        if (t < d) red[t] += red[t + d];
        __syncthreads();
    }
    if (t == 0) bsums[blockIdx.x] = red[0];
}

// ---- B) exclusive scan of the (<=64) block sums, in place -----------------
__global__ void scan_bsums_kernel(int* __restrict__ bsums, int nb) {
    __shared__ int sh[MAX_SCAN_BLOCKS];
    int t = threadIdx.x;
    int own = (t < nb) ? bsums[t] : 0;
    sh[t] = own;
    __syncthreads();
#pragma unroll
    for (int d = 1; d < MAX_SCAN_BLOCKS; d <<= 1) {
        int v = (t >= d) ? sh[t - d] : 0;
        __syncthreads();
        sh[t] += v;
        __syncthreads();
    }
    if (t < nb) bsums[t] = sh[t] - own;  // exclusive
}

// ---- C) per-block rescan + add block offset, write off/cur ----------------
__global__ __launch_bounds__(256) void scan_final_kernel(
    const int* __restrict__ cnt, const int* __restrict__ bsums,
    int* __restrict__ off, int* __restrict__ cur, int n) {
    __shared__ int vals[SCAN_TILE];
    __shared__ int tsum[256];
    int base = blockIdx.x * SCAN_TILE;
    int t = threadIdx.x;
#pragma unroll
    for (int j = 0; j < 16; j++) {
        int idx = base + j * 256 + t;
        vals[j * 256 + t] = (idx < n) ? cnt[idx] : 0;
    }
    __syncthreads();
    int loc[16];
    int s = 0;
#pragma unroll
    for (int j = 0; j < 16; j++) {
        loc[j] = s;
        s += vals[t * 16 + j];
    }
    int own = s;
    tsum[t] = s;
    __syncthreads();
#pragma unroll
    for (int d = 1; d < 256; d <<= 1) {
        int v = (t >= d) ? tsum[t - d] : 0;
        __syncthreads();
        tsum[t] += v;
        __syncthreads();
    }
    int pre = tsum[t] - own + bsums[blockIdx.x];
#pragma unroll
    for (int j = 0; j < 16; j++) {
        int idx = base + t * 16 + j;
        if (idx < n) {
            int v = pre + loc[j];
            off[idx] = v;
            cur[idx] = v;
        }
    }
    if (blockIdx.x == gridDim.x - 1 && t == 255) off[n] = pre + own;
}

__global__ void scatter_kernel(const int* __restrict__ src,
                               const int* __restrict__ dst, int E) {
    int e = blockIdx.x * blockDim.x + threadIdx.x;
    if (e < E) {
        int d = dst[e];
        int s = src[e];
        int p = atomicAdd(&g_cur1[d], 1);
        g_c1_src[p] = s;
        g_c1_eid[p] = e;
        int q = atomicAdd(&g_cur2[s], 1);
        g_c2_item[q] = d;
    }
}

// ---------------------------------------------------------------------------
// Input linears
// ---------------------------------------------------------------------------
__global__ __launch_bounds__(256) void user_lin_kernel(
    const float* __restrict__ x, const float* __restrict__ w,
    const float* __restrict__ b, int M) {
    __shared__ float ws[101 * 32];
    __shared__ float bs[32];
    for (int i = threadIdx.x; i < 101 * 32; i += 256) ws[i] = w[i];
    if (threadIdx.x < 32) bs[threadIdx.x] = b[threadIdx.x];
    __syncthreads();
    int c = threadIdx.x & 31;
    int r = blockIdx.x * 8 + (threadIdx.x >> 5);
    if (r >= M) return;
    const float* xr = x + (size_t)r * 101;
    float acc = bs[c];
#pragma unroll 4
    for (int k = 0; k < 101; k++) acc = fmaf(xr[k], ws[k * 32 + c], acc);
    g_user_x[(size_t)r * 32 + c] = acc;
}

__global__ void item_lin_kernel(const float* __restrict__ fx,
                                const float* __restrict__ w,
                                const float* __restrict__ b, int Ni) {
    int i = blockIdx.x * blockDim.x + threadIdx.x;
    if (i < Ni * 32) {
        int r = i >> 5, c = i & 31;
        g_item_x[i] = fmaf(fx[r], w[c], b[c]);
    }
}

// ---------------------------------------------------------------------------
// Register-tiled SGEMM with packed f32x2 FMAs (FFMA2, 2 MACs/issue):
// C[M,128] = A[M,K] @ W[K,128] + bias,  K in {32,128}
// BM=128, BN=128, BK=16, 256 threads, 8 rows x 4 col-pairs per thread
// ---------------------------------------------------------------------------
template <int K, bool RELU>
__global__ __launch_bounds__(256, 2) void sgemm_n128(
    const float* __restrict__ A, const float* __restrict__ W,
    const float* __restrict__ bias, float* __restrict__ C, int M) {
    __shared__ float As[16][132];  // [k][row], padded
    __shared__ float Ws[16][128];  // [k][col]
    const int tid = threadIdx.x;
    const int tx = tid & 15;   // col group
    const int ty = tid >> 4;   // row group
    const int row0 = blockIdx.x * 128;

    // acc2[i][j]: row (ty*8+i), col pair j -> {low: 2j-th, high: 2j+1-th}
    // of columns {tx*4, tx*4+1, tx*4+2, tx*4+3, 64+tx*4, ..., 64+tx*4+3}
    unsigned long long acc2[8][4];
#pragma unroll
    for (int i = 0; i < 8; i++)
#pragma unroll
        for (int j = 0; j < 4; j++) acc2[i][j] = 0ull;

    for (int k0 = 0; k0 < K; k0 += 16) {
        // A tile: 128 rows x 16 cols, transposed into As[k][row]
#pragma unroll
        for (int uu = tid; uu < 512; uu += 256) {
            int arow = uu >> 2;
            int ac = (uu & 3) << 2;
            float4 v = make_float4(0.f, 0.f, 0.f, 0.f);
            int gr = row0 + arow;
            if (gr < M) v = *(const float4*)(A + (size_t)gr * K + k0 + ac);
            As[ac + 0][arow] = v.x;
            As[ac + 1][arow] = v.y;
            As[ac + 2][arow] = v.z;
            As[ac + 3][arow] = v.w;
        }
        // W tile: 16 rows x 128 cols
#pragma unroll
        for (int uu = tid; uu < 512; uu += 256) {
            int wr = uu >> 5;
            int wc = (uu & 31) << 2;
            *(float4*)&Ws[wr][wc] =
                *(const float4*)(W + (size_t)(k0 + wr) * 128 + wc);
        }
        __syncthreads();
#pragma unroll
        for (int k = 0; k < 16; k++) {
            float4 a0 = *(const float4*)&As[k][ty * 8];
            float4 a1 = *(const float4*)&As[k][ty * 8 + 4];
            // packed W pairs straight from smem (16B aligned)
            const unsigned long long* wpa =
                (const unsigned long long*)&Ws[k][tx * 4];
            const unsigned long long* wpb =
                (const unsigned long long*)&Ws[k][64 + tx * 4];
            unsigned long long w2[4] = {wpa[0], wpa[1], wpb[0], wpb[1]};
            float a[8] = {a0.x, a0.y, a0.z, a0.w, a1.x, a1.y, a1.z, a1.w};
#pragma unroll
            for (int i = 0; i < 8; i++) {
                unsigned long long a2 = bcast2(a[i]);
                fma2(acc2[i][0], a2, w2[0]);
                fma2(acc2[i][1], a2, w2[1]);
                fma2(acc2[i][2], a2, w2[2]);
                fma2(acc2[i][3], a2, w2[3]);
            }
        }
        __syncthreads();
    }

    float b0[4], b1[4];
#pragma unroll
    for (int j = 0; j < 4; j++) {
        b0[j] = bias[tx * 4 + j];
        b1[j] = bias[64 + tx * 4 + j];
    }
#pragma unroll
    for (int i = 0; i < 8; i++) {
        int gr = row0 + ty * 8 + i;
        if (gr < M) {
            float c0, c1, c2, c3, c4, c5, c6, c7;
            unpack2(acc2[i][0], c0, c1);
            unpack2(acc2[i][1], c2, c3);
            unpack2(acc2[i][2], c4, c5);
            unpack2(acc2[i][3], c6, c7);
            float4 o0, o1;
            o0.x = c0 + b0[0]; o0.y = c1 + b0[1];
            o0.z = c2 + b0[2]; o0.w = c3 + b0[3];
            o1.x = c4 + b1[0]; o1.y = c5 + b1[1];
            o1.z = c6 + b1[2]; o1.w = c7 + b1[3];
            if (RELU) {
                o0.x = fmaxf(o0.x, 0.f); o0.y = fmaxf(o0.y, 0.f);
                o0.z = fmaxf(o0.z, 0.f); o0.w = fmaxf(o0.w, 0.f);
                o1.x = fmaxf(o1.x, 0.f); o1.y = fmaxf(o1.y, 0.f);
                o1.z = fmaxf(o1.z, 0.f); o1.w = fmaxf(o1.w, 0.f);
            }
            *(float4*)(C + (size_t)gr * 128 + tx * 4) = o0;
            *(float4*)(C + (size_t)gr * 128 + 64 + tx * 4) = o1;
        }
    }
}

// ---------------------------------------------------------------------------
// GATv2 edge aggregation, online softmax. One 128-thread CTA per dest node.
// warp = head h (4 heads), lane = channel c (32).
// ---------------------------------------------------------------------------
__global__ __launch_bounds__(128) void conv1_edge_kernel(
    const float* __restrict__ edge_attr, const float* __restrict__ we,
    const float* __restrict__ att, const float* __restrict__ bias) {
    int d = blockIdx.x;
    int tid = threadIdx.x;
    float xr   = g_xr1[d * 128 + tid];
    float attv = att[tid];
    float we0 = we[tid], we1 = we[128 + tid], we2 = we[256 + tid];
    int beg = g_off1[d], end = g_off1[d + 1];

    float m = -INFINITY, s = 0.f, acc = 0.f;

    float xlv = 0.f, e0 = 0.f, e1 = 0.f, e2 = 0.f;
    if (beg < end) {
        int srcn = g_c1_src[beg];
        int eid  = g_c1_eid[beg];
        xlv = g_xl1[(size_t)srcn * 128 + tid];
        e0 = edge_attr[(size_t)eid * 3 + 0];
        e1 = edge_attr[(size_t)eid * 3 + 1];
        e2 = edge_attr[(size_t)eid * 3 + 2];
    }
    for (int i = beg; i < end; i++) {
        float cxl = xlv, c0 = e0, c1 = e1, c2 = e2;
        int ni = i + 1;
        if (ni < end) {  // prefetch next edge while computing current
            int srcn = g_c1_src[ni];
            int eid  = g_c1_eid[ni];
            xlv = g_xl1[(size_t)srcn * 128 + tid];
            e0 = edge_attr[(size_t)eid * 3 + 0];
            e1 = edge_attr[(size_t)eid * 3 + 1];
            e2 = edge_attr[(size_t)eid * 3 + 2];
        }
        float mv = cxl + xr;
        mv = fmaf(c0, we0, mv);
        mv = fmaf(c1, we1, mv);
        mv = fmaf(c2, we2, mv);
        float g = mv > 0.f ? mv : NEG_SLOPE * mv;
        float p = g * attv;
#pragma unroll
        for (int o = 16; o; o >>= 1) p += __shfl_xor_sync(0xffffffffu, p, o);
        float logit = p;                     // same across the warp (= head)
        float nm = fmaxf(m, logit);
        float scale = __expf(m - nm);        // 0 when m == -inf
        float ev = __expf(logit - nm);
        s = s * scale + ev;
        acc = fmaf(ev, cxl, acc * scale);
        m = nm;
    }
    float o = (s > 0.f) ? acc / s : 0.f;
    o += bias[tid];
    g_item_h[d * 128 + tid] = fmaxf(o, 0.f);   // conv1 output has ReLU
}

__global__ __launch_bounds__(128) void conv2_edge_kernel(
    const float* __restrict__ att, const float* __restrict__ bias,
    float* __restrict__ user_out) {
    int u = blockIdx.x;
    int tid = threadIdx.x;
    float xr   = g_xr2[(size_t)u * 128 + tid];
    float attv = att[tid];
    int beg = g_off2[u], end = g_off2[u + 1];

    float m = -INFINITY, s = 0.f, acc = 0.f;

    float xlv = 0.f;
    if (beg < end) xlv = g_xl2[(size_t)g_c2_item[beg] * 128 + tid];
    for (int i = beg; i < end; i++) {
        float cxl = xlv;
        int ni = i + 1;
        if (ni < end) xlv = g_xl2[(size_t)g_c2_item[ni] * 128 + tid];
        float mv = cxl + xr;
        float g = mv > 0.f ? mv : NEG_SLOPE * mv;
        float p = g * attv;
#pragma unroll
        for (int o = 16; o; o >>= 1) p += __shfl_xor_sync(0xffffffffu, p, o);
        float logit = p;
        float nm = fmaxf(m, logit);
        float scale = __expf(m - nm);
        float ev = __expf(logit - nm);
        s = s * scale + ev;
        acc = fmaf(ev, cxl, acc * scale);
        m = nm;
    }
    float o = (s > 0.f) ? acc / s : 0.f;
    user_out[(size_t)u * 128 + tid] = o + bias[tid];  // no ReLU on conv2 output
}

// ---------------------------------------------------------------------------
// Launch
// ---------------------------------------------------------------------------
extern "C" void kernel_launch(void* const* d_in, const int* in_sizes, int n_in,
                              void* d_out, int out_size) {
    const float* customer_x = (const float*)d_in[0];
    const float* fund_x     = (const float*)d_in[1];
    const float* edge_attr  = (const float*)d_in[2];
    const float* user_lin_w = (const float*)d_in[3];
    const float* user_lin_b = (const float*)d_in[4];
    const float* item_lin_w = (const float*)d_in[5];
    const float* item_lin_b = (const float*)d_in[6];
    const float* conv1_wl   = (const float*)d_in[7];
    const float* conv1_bl   = (const float*)d_in[8];
    const float* conv1_wr   = (const float*)d_in[9];
    const float* conv1_br   = (const float*)d_in[10];
    const float* conv1_we   = (const float*)d_in[11];
    const float* conv1_att  = (const float*)d_in[12];
    const float* conv1_bias = (const float*)d_in[13];
    const float* conv2_wl   = (const float*)d_in[14];
    const float* conv2_bl   = (const float*)d_in[15];
    const float* conv2_wr   = (const float*)d_in[16];
    const float* conv2_br   = (const float*)d_in[17];
    const float* conv2_att  = (const float*)d_in[18];
    const float* conv2_bias = (const float*)d_in[19];
    const float* proj_w1    = (const float*)d_in[20];
    const float* proj_b1    = (const float*)d_in[21];
    const float* proj_w2    = (const float*)d_in[22];
    const float* proj_b2    = (const float*)d_in[23];
    const int*   edge_src   = (const int*)d_in[24];
    const int*   edge_dst   = (const int*)d_in[25];

    const int Nu = in_sizes[0] / 101;
    const int Ni = in_sizes[1];
    const int E  = in_sizes[24];

    float* user_out = (float*)d_out;                       // [Nu,128]
    float* z_out    = (float*)d_out + (size_t)Nu * 128;    // [Nu,128]

    const int TB = 256;
    const int gE = (E + TB - 1) / TB;

    // --- CSR build ---
    zero_counts_kernel<<<(Nu + TB - 1) / TB, TB>>>(Ni, Nu);
    hist_kernel<<<gE, TB>>>(edge_src, edge_dst, E);
    {
        int *cnt1, *off1, *cur1, *cnt2, *off2, *cur2, *bs1, *bs2;
        cudaGetSymbolAddress((void**)&cnt1, g_cnt1);
        cudaGetSymbolAddress((void**)&off1, g_off1);
        cudaGetSymbolAddress((void**)&cur1, g_cur1);
        cudaGetSymbolAddress((void**)&cnt2, g_cnt2);
        cudaGetSymbolAddress((void**)&off2, g_off2);
        cudaGetSymbolAddress((void**)&cur2, g_cur2);
        cudaGetSymbolAddress((void**)&bs1, g_bsums1);
        cudaGetSymbolAddress((void**)&bs2, g_bsums2);
        int nb1 = (Ni + SCAN_TILE - 1) / SCAN_TILE;
        int nb2 = (Nu + SCAN_TILE - 1) / SCAN_TILE;
        scan_part_kernel<<<nb1, 256>>>(cnt1, bs1, Ni);
        scan_part_kernel<<<nb2, 256>>>(cnt2, bs2, Nu);
        scan_bsums_kernel<<<1, MAX_SCAN_BLOCKS>>>(bs1, nb1);
        scan_bsums_kernel<<<1, MAX_SCAN_BLOCKS>>>(bs2, nb2);
        scan_final_kernel<<<nb1, 256>>>(cnt1, bs1, off1, cur1, Ni);
        scan_final_kernel<<<nb2, 256>>>(cnt2, bs2, off2, cur2, Nu);
    }
    scatter_kernel<<<gE, TB>>>(edge_src, edge_dst, E);

    // --- input linears ---
    user_lin_kernel<<<(Nu + 7) / 8, 256>>>(customer_x, user_lin_w, user_lin_b, Nu);
    item_lin_kernel<<<(Ni * 32 + TB - 1) / TB, TB>>>(fund_x, item_lin_w, item_lin_b, Ni);

    // --- conv1 projections ---
    {
        float *ux, *ix, *xl1, *xr1;
        cudaGetSymbolAddress((void**)&ux, g_user_x);
        cudaGetSymbolAddress((void**)&ix, g_item_x);
        cudaGetSymbolAddress((void**)&xl1, g_xl1);
        cudaGetSymbolAddress((void**)&xr1, g_xr1);
        sgemm_n128<32, false><<<(Nu + 127) / 128, 256>>>(ux, conv1_wl, conv1_bl, xl1, Nu);
        sgemm_n128<32, false><<<(Ni + 127) / 128, 256>>>(ix, conv1_wr, conv1_br, xr1, Ni);
    }

    // --- conv1 edge aggregation (user -> item), fused edge_proj, ReLU ---
    conv1_edge_kernel<<<Ni, 128>>>(edge_attr, conv1_we, conv1_att, conv1_bias);

    // --- conv2 projections ---
    {
        float *ih, *ux, *xl2, *xr2;
        cudaGetSymbolAddress((void**)&ih, g_item_h);
        cudaGetSymbolAddress((void**)&ux, g_user_x);
        cudaGetSymbolAddress((void**)&xl2, g_xl2);
        cudaGetSymbolAddress((void**)&xr2, g_xr2);
        sgemm_n128<128, false><<<(Ni + 127) / 128, 256>>>(ih, conv2_wl, conv2_bl, xl2, Ni);
        sgemm_n128<32, false><<<(Nu + 127) / 128, 256>>>(ux, conv2_wr, conv2_br, xr2, Nu);
    }

    // --- conv2 edge aggregation (item -> user) -> user_out (first output) ---
    conv2_edge_kernel<<<Nu, 128>>>(conv2_att, conv2_bias, user_out);

    // --- projection head: z = relu(user_out @ W1 + b1) @ W2 + b2 ---
    {
        float* tmp;
        cudaGetSymbolAddress((void**)&tmp, g_tmp);
        sgemm_n128<128, true><<<(Nu + 127) / 128, 256>>>(user_out, proj_w1, proj_b1, tmp, Nu);
        sgemm_n128<128, false><<<(Nu + 127) / 128, 256>>>(tmp, proj_w2, proj_b2, z_out, Nu);
    }
}